// round 1
// baseline (speedup 1.0000x reference)
#include <cuda_runtime.h>
#include <cstdint>

// Problem constants
#define TLEN   128
#define THID   64
#define TB     256
#define TN     2048
#define MTILE  64          // rows per block (divides TN, so a block never straddles a batch)
#define NEGF   (-1.0e9f)

// -------- device scratch (allocation-free rule: __device__ global) --------
__device__ int g_pool[TB * TLEN];   // per-batch column max, stored as float bits
                                    // (all candidates are >=0 or exactly -1e9, so
                                    // signed-int compare == float compare)

// Shared memory layout (floats)
#define OFF_XT    0                       // [128][68]  X transposed (k-major)
#define OFF_W1    (OFF_XT + 128*68)       // [128][64]
#define OFF_W2    (OFF_W1 + 128*64)       // [64][128]
#define OFF_H1    (OFF_W2 + 64*128)       // [64][68]   H1 transposed (k-major)
#define OFF_RS    (OFF_H1 + 64*68)        // [64][16]   partial row sums
#define OFF_RQ    (OFF_RS + 64*16)        // [64][16]   partial row sumsq
#define OFF_MU    (OFF_RQ + 64*16)        // [64]
#define OFF_RSD   (OFF_MU + 64)           // [64]
#define OFF_POOL  (OFF_RSD + 64)          // [128] ints
#define OFF_B1    (OFF_POOL + 128)        // [64]
#define OFF_B2    (OFF_B1 + 64)           // [128]
#define OFF_G     (OFF_B2 + 128)          // [128]
#define OFF_BT    (OFF_G + 128)           // [128]
#define OFF_MASK  (OFF_BT + 128)          // [64] ints
#define SMEM_FLOATS (OFF_MASK + 64)
#define SMEM_BYTES  (SMEM_FLOATS * 4)

__global__ void pool_init_kernel() {
    int i = blockIdx.x * blockDim.x + threadIdx.x;
    if (i < TB * TLEN) g_pool[i] = __float_as_int(NEGF);
}

__global__ __launch_bounds__(256, 1)
void fused_mlp_kernel(const float* __restrict__ X,
                      const int*   __restrict__ Mk,
                      const float* __restrict__ W1g,
                      const float* __restrict__ b1g,
                      const float* __restrict__ W2g,
                      const float* __restrict__ b2g,
                      const float* __restrict__ gg,
                      const float* __restrict__ btg,
                      float* __restrict__ out)
{
    extern __shared__ float sm[];
    float* sXt  = sm + OFF_XT;
    float* sW1  = sm + OFF_W1;
    float* sW2  = sm + OFF_W2;
    float* sH1  = sm + OFF_H1;
    float* sRS  = sm + OFF_RS;
    float* sRQ  = sm + OFF_RQ;
    float* sMu  = sm + OFF_MU;
    float* sRsd = sm + OFF_RSD;
    int*   sPool = (int*)(sm + OFF_POOL);
    float* sB1  = sm + OFF_B1;
    float* sB2  = sm + OFF_B2;
    float* sG   = sm + OFF_G;
    float* sBt  = sm + OFF_BT;
    int*   sMask = (int*)(sm + OFF_MASK);

    const int tid  = threadIdx.x;
    const int row0 = blockIdx.x * MTILE;
    const int bidx = row0 >> 11;           // row0 / 2048

    // small params + pool init
    if (tid < 128) {
        sPool[tid] = __float_as_int(NEGF);
        sB2[tid] = b2g[tid];
        sG[tid]  = gg[tid];
        sBt[tid] = btg[tid];
    } else {
        int t = tid - 128;
        if (t < 64) { sB1[t] = b1g[t]; sMask[t] = Mk[row0 + t]; }
    }

    // weights -> shared (row-major copies, vectorized)
    {
        const float4* gW1 = (const float4*)W1g;
        const float4* gW2 = (const float4*)W2g;
        #pragma unroll
        for (int v = 0; v < 8; v++) {
            ((float4*)sW1)[tid + 256 * v] = gW1[tid + 256 * v];
            ((float4*)sW2)[tid + 256 * v] = gW2[tid + 256 * v];
        }
    }
    // X tile -> shared, transposed to k-major [k][r]
    {
        int r  = tid >> 2;                 // 0..63
        int kb = (tid & 3) << 5;           // 0,32,64,96
        const float* gx = X + (size_t)(row0 + r) * TLEN + kb;
        #pragma unroll
        for (int v = 0; v < 8; v++) {
            float4 x = *(const float4*)(gx + 4 * v);
            int k = kb + 4 * v;
            sXt[(k + 0) * 68 + r] = x.x;
            sXt[(k + 1) * 68 + r] = x.y;
            sXt[(k + 2) * 68 + r] = x.z;
            sXt[(k + 3) * 68 + r] = x.w;
        }
    }
    __syncthreads();

    const int tr = tid >> 4;   // 0..15
    const int tc = tid & 15;   // 0..15

    // ---------------- GEMM1: H1[64x64] = X[64x128] @ W1[128x64] ----------------
    {
        const int r0 = tr * 4, c0 = tc * 4;
        float acc[4][4];
        #pragma unroll
        for (int i = 0; i < 4; i++)
            #pragma unroll
            for (int j = 0; j < 4; j++) acc[i][j] = 0.f;

        #pragma unroll 4
        for (int k = 0; k < 128; k++) {
            float4 a = *(const float4*)(sXt + k * 68 + r0);
            float4 w = *(const float4*)(sW1 + k * 64 + c0);
            float av[4] = {a.x, a.y, a.z, a.w};
            float wv[4] = {w.x, w.y, w.z, w.w};
            #pragma unroll
            for (int i = 0; i < 4; i++)
                #pragma unroll
                for (int j = 0; j < 4; j++)
                    acc[i][j] += av[i] * wv[j];
        }
        // + b1, store transposed [k=c][r]
        #pragma unroll
        for (int j = 0; j < 4; j++) {
            float bb = sB1[c0 + j];
            #pragma unroll
            for (int i = 0; i < 4; i++)
                sH1[(c0 + j) * 68 + (r0 + i)] = acc[i][j] + bb;
        }
    }
    __syncthreads();

    // ---------------- GEMM2: H2[64x128] = H1[64x64] @ W2[64x128] ----------------
    const int r0 = tr * 4, c0 = tc * 8;
    float acc[4][8];
    #pragma unroll
    for (int i = 0; i < 4; i++)
        #pragma unroll
        for (int j = 0; j < 8; j++) acc[i][j] = 0.f;

    #pragma unroll 2
    for (int k = 0; k < 64; k++) {
        float4 a  = *(const float4*)(sH1 + k * 68 + r0);
        float4 w0 = *(const float4*)(sW2 + k * 128 + c0);
        float4 w1 = *(const float4*)(sW2 + k * 128 + c0 + 4);
        float av[4] = {a.x, a.y, a.z, a.w};
        float wv[8] = {w0.x, w0.y, w0.z, w0.w, w1.x, w1.y, w1.z, w1.w};
        #pragma unroll
        for (int i = 0; i < 4; i++)
            #pragma unroll
            for (int j = 0; j < 8; j++)
                acc[i][j] += av[i] * wv[j];
    }

    // + b2, partial row sums for LayerNorm
    {
        float s[4] = {0.f, 0.f, 0.f, 0.f}, q[4] = {0.f, 0.f, 0.f, 0.f};
        #pragma unroll
        for (int j = 0; j < 8; j++) {
            float bb = sB2[c0 + j];
            #pragma unroll
            for (int i = 0; i < 4; i++) {
                acc[i][j] += bb;
                s[i] += acc[i][j];
                q[i] += acc[i][j] * acc[i][j];
            }
        }
        #pragma unroll
        for (int i = 0; i < 4; i++) {
            sRS[(r0 + i) * 16 + tc] = s[i];
            sRQ[(r0 + i) * 16 + tc] = q[i];
        }
    }
    __syncthreads();

    if (tid < 64) {
        float S = 0.f, Q = 0.f;
        #pragma unroll
        for (int t = 0; t < 16; t++) { S += sRS[tid * 16 + t]; Q += sRQ[tid * 16 + t]; }
        float mu  = S * 0.0078125f;                 // /128
        float var = Q * 0.0078125f - mu * mu;
        sMu[tid]  = mu;
        sRsd[tid] = rsqrtf(var + 1e-3f);            // keras LN eps
    }
    __syncthreads();

    // normalize + relu + mask-fill + store x + column max
    float cm[8];
    #pragma unroll
    for (int j = 0; j < 8; j++) cm[j] = NEGF;

    #pragma unroll
    for (int i = 0; i < 4; i++) {
        int r = r0 + i;
        float mu = sMu[r], rs = sRsd[r];
        bool mk = (sMask[r] != 0);
        float v[8];
        #pragma unroll
        for (int j = 0; j < 8; j++) {
            float t = (acc[i][j] - mu) * rs * sG[c0 + j] + sBt[c0 + j];
            t = fmaxf(t, 0.f);
            v[j] = mk ? t : NEGF;
            cm[j] = fmaxf(cm[j], v[j]);
        }
        float* op = out + (size_t)(row0 + r) * 256 + c0;
        *(float4*)(op)     = make_float4(v[0], v[1], v[2], v[3]);
        *(float4*)(op + 4) = make_float4(v[4], v[5], v[6], v[7]);
    }
    #pragma unroll
    for (int j = 0; j < 8; j++)
        atomicMax(&sPool[c0 + j], __float_as_int(cm[j]));
    __syncthreads();

    if (tid < 128)
        atomicMax(&g_pool[bidx * 128 + tid], sPool[tid]);
}

// second half of output: broadcast per-batch pooled max
__global__ void bcast_kernel(float* __restrict__ out) {
    int i   = blockIdx.x * blockDim.x + threadIdx.x;  // over B*N*32 float4s
    int d4  = (i & 31) << 2;
    int row = i >> 5;
    int bb  = row >> 11;
    int4 p = *(const int4*)(g_pool + bb * 128 + d4);
    float4 v = make_float4(__int_as_float(p.x), __int_as_float(p.y),
                           __int_as_float(p.z), __int_as_float(p.w));
    *(float4*)(out + (size_t)row * 256 + 128 + d4) = v;
}

extern "C" void kernel_launch(void* const* d_in, const int* in_sizes, int n_in,
                              void* d_out, int out_size) {
    const float* X  = (const float*)d_in[0];
    const int*   Mk = (const int*)  d_in[1];
    const float* W1 = (const float*)d_in[2];
    const float* b1 = (const float*)d_in[3];
    const float* W2 = (const float*)d_in[4];
    const float* b2 = (const float*)d_in[5];
    const float* g  = (const float*)d_in[6];
    const float* bt = (const float*)d_in[7];
    float* out = (float*)d_out;

    cudaFuncSetAttribute(fused_mlp_kernel,
                         cudaFuncAttributeMaxDynamicSharedMemorySize, SMEM_BYTES);

    pool_init_kernel<<<(TB * TLEN + 255) / 256, 256>>>();
    fused_mlp_kernel<<<(TB * TN) / MTILE, 256, SMEM_BYTES>>>(
        X, Mk, W1, b1, W2, b2, g, bt, out);
    bcast_kernel<<<(TB * TN * 32) / 256, 256>>>(out);
}

// round 3
// speedup vs baseline: 3.1843x; 3.1843x over previous
#include <cuda_runtime.h>
#include <cuda_bf16.h>
#include <cstdint>

#define TLEN   128
#define THID   64
#define TB     256
#define TN     2048
#define NEGF   (-1.0e9f)

// ---------- device scratch (allocation-free rule) ----------
__device__ int           g_pool[TB * TLEN];
__device__ __nv_bfloat16 g_W1bf[128 * 64];
__device__ __nv_bfloat16 g_W2bf[64 * 128];

// ---------- smem layout (bytes) ----------
#define O_X    0                         // [64][136] bf16
#define O_W1   (O_X   + 64*136*2)        // [128][72] bf16
#define O_W2   (O_W1  + 128*72*2)        // [64][136] bf16
#define O_H1   (O_W2  + 64*136*2)        // [64][72]  bf16
#define O_RS   (O_H1  + 64*72*2)         // [64][2] f32
#define O_RQ   (O_RS  + 512)
#define O_MU   (O_RQ  + 512)             // [64] f32
#define O_RSD  (O_MU  + 256)
#define O_POOL (O_RSD + 256)             // [128] int
#define O_B2   (O_POOL+ 512)             // [128] f32
#define O_G    (O_B2  + 512)
#define O_BT   (O_G   + 512)
#define O_B1   (O_BT  + 512)             // [64] f32
#define O_MASK (O_B1  + 256)             // [64] int
#define SMEM_BYTES (O_MASK + 256)

__device__ __forceinline__ uint32_t smem_u32(const void* p) {
    uint32_t a;
    asm("{ .reg .u64 t; cvta.to.shared.u64 t, %1; cvt.u32.u64 %0, t; }" : "=r"(a) : "l"(p));
    return a;
}
__device__ __forceinline__ void ldmA(uint32_t* r, uint32_t addr) {
    asm volatile("ldmatrix.sync.aligned.m8n8.x4.shared.b16 {%0,%1,%2,%3}, [%4];"
        : "=r"(r[0]),"=r"(r[1]),"=r"(r[2]),"=r"(r[3]) : "r"(addr));
}
__device__ __forceinline__ void ldmBT(uint32_t* r, uint32_t addr) {
    asm volatile("ldmatrix.sync.aligned.m8n8.x4.trans.shared.b16 {%0,%1,%2,%3}, [%4];"
        : "=r"(r[0]),"=r"(r[1]),"=r"(r[2]),"=r"(r[3]) : "r"(addr));
}
__device__ __forceinline__ void mma16816(float* c, const uint32_t* a, const uint32_t* b) {
    asm volatile("mma.sync.aligned.m16n8k16.row.col.f32.bf16.bf16.f32 "
        "{%0,%1,%2,%3}, {%4,%5,%6,%7}, {%8,%9}, {%0,%1,%2,%3};"
        : "+f"(c[0]),"+f"(c[1]),"+f"(c[2]),"+f"(c[3])
        : "r"(a[0]),"r"(a[1]),"r"(a[2]),"r"(a[3]), "r"(b[0]),"r"(b[1]));
}

// prep: convert weights to bf16 + init global pool
__global__ void prep_kernel(const float* __restrict__ W1, const float* __restrict__ W2) {
    int i = blockIdx.x * blockDim.x + threadIdx.x;
    if (i < 128 * 64) g_W1bf[i] = __float2bfloat16(W1[i]);
    if (i < 64 * 128) g_W2bf[i] = __float2bfloat16(W2[i]);
    if (i < TB * TLEN) g_pool[i] = __float_as_int(NEGF);
}

__global__ __launch_bounds__(256)
void fused_mlp_kernel(const float* __restrict__ X,
                      const int*   __restrict__ Mk,
                      const float* __restrict__ b1g,
                      const float* __restrict__ b2g,
                      const float* __restrict__ gg,
                      const float* __restrict__ btg,
                      float* __restrict__ out)
{
    extern __shared__ char smc[];
    const uint32_t sb = smem_u32(smc);
    const int tid  = threadIdx.x;
    const int lane = tid & 31, warp = tid >> 5;
    const int row0 = blockIdx.x * 64;
    const int bidx = row0 >> 11;

    float* fRS  = (float*)(smc + O_RS);
    float* fRQ  = (float*)(smc + O_RQ);
    float* fMu  = (float*)(smc + O_MU);
    float* fRsd = (float*)(smc + O_RSD);
    int*   iPool= (int*)  (smc + O_POOL);
    float* fB1  = (float*)(smc + O_B1);
    float* fB2  = (float*)(smc + O_B2);
    float* fG   = (float*)(smc + O_G);
    float* fBt  = (float*)(smc + O_BT);
    int*   iMask= (int*)  (smc + O_MASK);

    // ---- small params ----
    if (tid < 128) {
        iPool[tid] = __float_as_int(NEGF);
        fB2[tid] = b2g[tid];
        fG[tid]  = gg[tid];
        fBt[tid] = btg[tid];
    } else {
        int t = tid - 128;
        if (t < 64) { fB1[t] = b1g[t]; iMask[t] = Mk[row0 + t]; }
    }

    // ---- X tile: f32 -> bf16, [64][136] ----
    {
        __nv_bfloat16* sX = (__nv_bfloat16*)(smc + O_X);
        const float4* gX = (const float4*)(X + (size_t)row0 * TLEN);
        #pragma unroll
        for (int v = 0; v < 8; v++) {
            int idx = tid + 256 * v;
            int r = idx >> 5, c = (idx & 31) * 4;
            float4 x = gX[idx];
            __nv_bfloat162* p = (__nv_bfloat162*)(sX + r * 136 + c);
            p[0] = __floats2bfloat162_rn(x.x, x.y);
            p[1] = __floats2bfloat162_rn(x.z, x.w);
        }
    }
    // ---- W1 bf16 -> [128][72], W2 bf16 -> [64][136] ----
    {
        const uint32_t* gw1 = (const uint32_t*)g_W1bf;
        const uint32_t* gw2 = (const uint32_t*)g_W2bf;
        #pragma unroll
        for (int v = 0; v < 16; v++) {
            int i = tid + 256 * v;
            int k1 = i >> 5, c1 = (i & 31) * 2;
            *(uint32_t*)(smc + O_W1 + k1 * 144 + c1 * 2) = gw1[i];
            int k2 = i >> 6, c2 = (i & 63) * 2;
            *(uint32_t*)(smc + O_W2 + k2 * 272 + c2 * 2) = gw2[i];
        }
    }
    __syncthreads();

    const int g = lane >> 2, t = lane & 3;
    const int mt = warp & 3;          // m-tile (16 rows)
    const int nh = warp >> 2;         // n-half
    const int r0 = mt * 16;
    // ldmatrix lane address components
    const int am = ((lane >> 3) & 1) * 8 + (lane & 7);   // row offset for A
    const int ak = ((lane >> 4) & 1) * 8;                // k offset for A
    const int bk = am;                                   // k offset for B (trans)
    const int bn = ak;                                   // n offset for B (trans)

    // ================= GEMM1: H1[64x64] = X @ W1 =================
    {
        const int cb1 = nh * 32;
        float c1[4][4];
        #pragma unroll
        for (int j = 0; j < 4; j++)
            #pragma unroll
            for (int q = 0; q < 4; q++) c1[j][q] = 0.f;

        uint32_t aB = sb + O_X  + (r0 + am) * 272 + ak * 2;
        uint32_t bB = sb + O_W1 + bk * 144 + (cb1 + bn) * 2;
        #pragma unroll
        for (int ks = 0; ks < 8; ks++) {
            uint32_t a[4], b[8];
            ldmA(a, aB + ks * 32);
            ldmBT(b,     bB + ks * (16 * 144));
            ldmBT(b + 4, bB + ks * (16 * 144) + 32);
            mma16816(c1[0], a, b);
            mma16816(c1[1], a, b + 2);
            mma16816(c1[2], a, b + 4);
            mma16816(c1[3], a, b + 6);
        }
        // +b1, convert to bf16, store H1 [64][72]
        #pragma unroll
        for (int j = 0; j < 4; j++) {
            int c = cb1 + j * 8 + 2 * t;
            float bb0 = fB1[c], bb1 = fB1[c + 1];
            __nv_bfloat162 lo = __floats2bfloat162_rn(c1[j][0] + bb0, c1[j][1] + bb1);
            __nv_bfloat162 hi = __floats2bfloat162_rn(c1[j][2] + bb0, c1[j][3] + bb1);
            *(__nv_bfloat162*)(smc + O_H1 + (r0 + g) * 144 + c * 2)     = lo;
            *(__nv_bfloat162*)(smc + O_H1 + (r0 + g + 8) * 144 + c * 2) = hi;
        }
    }
    __syncthreads();

    // ================= GEMM2: H2[64x128] = H1 @ W2 =================
    const int cb2 = nh * 64;
    float c2[8][4];
    #pragma unroll
    for (int j = 0; j < 8; j++)
        #pragma unroll
        for (int q = 0; q < 4; q++) c2[j][q] = 0.f;

    {
        uint32_t aB = sb + O_H1 + (r0 + am) * 144 + ak * 2;
        uint32_t bB = sb + O_W2 + bk * 272 + (cb2 + bn) * 2;
        #pragma unroll
        for (int ks = 0; ks < 4; ks++) {
            uint32_t a[4];
            ldmA(a, aB + ks * 32);
            #pragma unroll
            for (int jj = 0; jj < 4; jj++) {
                uint32_t b[4];
                ldmBT(b, bB + ks * (16 * 272) + jj * 32);
                mma16816(c2[2 * jj],     a, b);
                mma16816(c2[2 * jj + 1], a, b + 2);
            }
        }
    }

    // ---- +b2, LN partial sums ----
    {
        float sl = 0.f, ql = 0.f, sh = 0.f, qh = 0.f;
        #pragma unroll
        for (int j = 0; j < 8; j++) {
            int c = cb2 + j * 8 + 2 * t;
            float bb0 = fB2[c], bb1 = fB2[c + 1];
            c2[j][0] += bb0; c2[j][1] += bb1;
            c2[j][2] += bb0; c2[j][3] += bb1;
            sl += c2[j][0] + c2[j][1];
            ql += c2[j][0] * c2[j][0] + c2[j][1] * c2[j][1];
            sh += c2[j][2] + c2[j][3];
            qh += c2[j][2] * c2[j][2] + c2[j][3] * c2[j][3];
        }
        #pragma unroll
        for (int s = 1; s <= 2; s <<= 1) {
            sl += __shfl_xor_sync(0xffffffffu, sl, s);
            ql += __shfl_xor_sync(0xffffffffu, ql, s);
            sh += __shfl_xor_sync(0xffffffffu, sh, s);
            qh += __shfl_xor_sync(0xffffffffu, qh, s);
        }
        if (t == 0) {
            fRS[(r0 + g) * 2 + nh] = sl;     fRQ[(r0 + g) * 2 + nh] = ql;
            fRS[(r0 + g + 8) * 2 + nh] = sh; fRQ[(r0 + g + 8) * 2 + nh] = qh;
        }
    }
    __syncthreads();

    if (tid < 64) {
        float S = fRS[tid * 2] + fRS[tid * 2 + 1];
        float Q = fRQ[tid * 2] + fRQ[tid * 2 + 1];
        float mu  = S * 0.0078125f;
        float var = Q * 0.0078125f - mu * mu;
        fMu[tid]  = mu;
        fRsd[tid] = rsqrtf(var + 1e-3f);
    }
    __syncthreads();

    // ---- normalize + relu + mask + store + pool ----
    {
        const float muL = fMu[r0 + g],     rsL = fRsd[r0 + g];
        const float muH = fMu[r0 + g + 8], rsH = fRsd[r0 + g + 8];
        const bool  mkL = (iMask[r0 + g] != 0);
        const bool  mkH = (iMask[r0 + g + 8] != 0);
        float* oL = out + (size_t)(row0 + r0 + g) * 256;
        float* oH = out + (size_t)(row0 + r0 + g + 8) * 256;

        #pragma unroll
        for (int j = 0; j < 8; j++) {
            int c = cb2 + j * 8 + 2 * t;
            float ga0 = fG[c], ga1 = fG[c + 1];
            float be0 = fBt[c], be1 = fBt[c + 1];

            float vL0 = fmaxf((c2[j][0] - muL) * rsL * ga0 + be0, 0.f);
            float vL1 = fmaxf((c2[j][1] - muL) * rsL * ga1 + be1, 0.f);
            float vH0 = fmaxf((c2[j][2] - muH) * rsH * ga0 + be0, 0.f);
            float vH1 = fmaxf((c2[j][3] - muH) * rsH * ga1 + be1, 0.f);
            vL0 = mkL ? vL0 : NEGF;  vL1 = mkL ? vL1 : NEGF;
            vH0 = mkH ? vH0 : NEGF;  vH1 = mkH ? vH1 : NEGF;

            *(float2*)(oL + c) = make_float2(vL0, vL1);
            *(float2*)(oH + c) = make_float2(vH0, vH1);

            float pm0 = fmaxf(vL0, vH0), pm1 = fmaxf(vL1, vH1);
            #pragma unroll
            for (int s = 4; s <= 16; s <<= 1) {
                pm0 = fmaxf(pm0, __shfl_xor_sync(0xffffffffu, pm0, s));
                pm1 = fmaxf(pm1, __shfl_xor_sync(0xffffffffu, pm1, s));
            }
            if (g == 0) {
                atomicMax(&iPool[c],     __float_as_int(pm0));
                atomicMax(&iPool[c + 1], __float_as_int(pm1));
            }
        }
    }
    __syncthreads();

    if (tid < 128)
        atomicMax(&g_pool[bidx * 128 + tid], iPool[tid]);
}

// second half of output: broadcast per-batch pooled max
__global__ void bcast_kernel(float* __restrict__ out) {
    int i   = blockIdx.x * blockDim.x + threadIdx.x;  // over B*N*32 float4s
    int d4  = (i & 31) << 2;
    int row = i >> 5;
    int bb  = row >> 11;
    int4 p = *(const int4*)(g_pool + bb * 128 + d4);
    float4 v = make_float4(__int_as_float(p.x), __int_as_float(p.y),
                           __int_as_float(p.z), __int_as_float(p.w));
    *(float4*)(out + (size_t)row * 256 + 128 + d4) = v;
}

extern "C" void kernel_launch(void* const* d_in, const int* in_sizes, int n_in,
                              void* d_out, int out_size) {
    const float* X  = (const float*)d_in[0];
    const int*   Mk = (const int*)  d_in[1];
    const float* W1 = (const float*)d_in[2];
    const float* b1 = (const float*)d_in[3];
    const float* W2 = (const float*)d_in[4];
    const float* b2 = (const float*)d_in[5];
    const float* g  = (const float*)d_in[6];
    const float* bt = (const float*)d_in[7];
    float* out = (float*)d_out;

    cudaFuncSetAttribute(fused_mlp_kernel,
                         cudaFuncAttributeMaxDynamicSharedMemorySize, SMEM_BYTES);

    prep_kernel<<<(TB * TLEN + 255) / 256, 256>>>(W1, W2);
    fused_mlp_kernel<<<(TB * TN) / 64, 256, SMEM_BYTES>>>(
        X, Mk, b1, b2, g, bt, out);
    bcast_kernel<<<(TB * TN * 32) / 256, 256>>>(out);
}

// round 4
// speedup vs baseline: 3.8139x; 1.1977x over previous
#include <cuda_runtime.h>
#include <cuda_bf16.h>
#include <cstdint>

#define TLEN   128
#define THID   64
#define TB     256
#define TN     2048
#define NEGF   (-1.0e9f)
#define NTILE  4            // 64-row tiles per block
#define ROWS_PB (NTILE*64)  // 256 rows per block

// ---------- device scratch (allocation-free rule) ----------
__device__ int           g_pool[TB * TLEN];
__device__ __nv_bfloat16 g_W1bf[128 * 64];
__device__ __nv_bfloat16 g_W2bf[64 * 128];

// ---------- smem layout (bytes) ----------
#define O_X    0                         // [64][136] bf16
#define O_W1   (O_X   + 64*136*2)        // [128][72] bf16
#define O_W2   (O_W1  + 128*72*2)        // [64][136] bf16
#define O_H1   (O_W2  + 64*136*2)        // [64][72]  bf16
#define O_RS   (O_H1  + 64*72*2)         // [64][2] f32
#define O_RQ   (O_RS  + 512)
#define O_MU   (O_RQ  + 512)             // [64] f32
#define O_RSD  (O_MU  + 256)
#define O_POOL (O_RSD + 256)             // [128] int
#define O_B2   (O_POOL+ 512)             // [128] f32
#define O_G    (O_B2  + 512)
#define O_BT   (O_G   + 512)
#define O_B1   (O_BT  + 512)             // [64] f32
#define SMEM_BYTES (O_B1 + 256)

__device__ __forceinline__ uint32_t smem_u32(const void* p) {
    uint32_t a;
    asm("{ .reg .u64 t; cvta.to.shared.u64 t, %1; cvt.u32.u64 %0, t; }" : "=r"(a) : "l"(p));
    return a;
}
__device__ __forceinline__ void ldmA(uint32_t* r, uint32_t addr) {
    asm volatile("ldmatrix.sync.aligned.m8n8.x4.shared.b16 {%0,%1,%2,%3}, [%4];"
        : "=r"(r[0]),"=r"(r[1]),"=r"(r[2]),"=r"(r[3]) : "r"(addr));
}
__device__ __forceinline__ void ldmBT(uint32_t* r, uint32_t addr) {
    asm volatile("ldmatrix.sync.aligned.m8n8.x4.trans.shared.b16 {%0,%1,%2,%3}, [%4];"
        : "=r"(r[0]),"=r"(r[1]),"=r"(r[2]),"=r"(r[3]) : "r"(addr));
}
__device__ __forceinline__ void mma16816(float* c, const uint32_t* a, const uint32_t* b) {
    asm volatile("mma.sync.aligned.m16n8k16.row.col.f32.bf16.bf16.f32 "
        "{%0,%1,%2,%3}, {%4,%5,%6,%7}, {%8,%9}, {%0,%1,%2,%3};"
        : "+f"(c[0]),"+f"(c[1]),"+f"(c[2]),"+f"(c[3])
        : "r"(a[0]),"r"(a[1]),"r"(a[2]),"r"(a[3]), "r"(b[0]),"r"(b[1]));
}

// prep: convert weights to bf16 + init global pool
__global__ void prep_kernel(const float* __restrict__ W1, const float* __restrict__ W2) {
    int i = blockIdx.x * blockDim.x + threadIdx.x;
    if (i < 128 * 64) g_W1bf[i] = __float2bfloat16(W1[i]);
    if (i < 64 * 128) g_W2bf[i] = __float2bfloat16(W2[i]);
    if (i < TB * TLEN) g_pool[i] = __float_as_int(NEGF);
}

__global__ __launch_bounds__(256, 2)
void fused_mlp_kernel(const float* __restrict__ X,
                      const int*   __restrict__ Mk,
                      const float* __restrict__ b1g,
                      const float* __restrict__ b2g,
                      const float* __restrict__ gg,
                      const float* __restrict__ btg,
                      float* __restrict__ out)
{
    extern __shared__ char smc[];
    const uint32_t sb = smem_u32(smc);
    const int tid  = threadIdx.x;
    const int lane = tid & 31, warp = tid >> 5;
    const int base = blockIdx.x * ROWS_PB;     // block handles rows [base, base+256)
    const int bidx = base >> 11;               // batch index (ROWS_PB divides 2048)

    float* fRS  = (float*)(smc + O_RS);
    float* fRQ  = (float*)(smc + O_RQ);
    float* fMu  = (float*)(smc + O_MU);
    float* fRsd = (float*)(smc + O_RSD);
    int*   iPool= (int*)  (smc + O_POOL);
    float* fB1  = (float*)(smc + O_B1);
    float* fB2  = (float*)(smc + O_B2);
    float* fG   = (float*)(smc + O_G);
    float* fBt  = (float*)(smc + O_BT);

    // ---- small params ----
    if (tid < 128) {
        iPool[tid] = __float_as_int(NEGF);
        fB2[tid] = b2g[tid];
        fG[tid]  = gg[tid];
        fBt[tid] = btg[tid];
    } else if (tid - 128 < 64) {
        fB1[tid - 128] = b1g[tid - 128];
    }

    // ---- weights once per block: W1 -> [128][72], W2 -> [64][136] ----
    {
        const uint32_t* gw1 = (const uint32_t*)g_W1bf;
        const uint32_t* gw2 = (const uint32_t*)g_W2bf;
        #pragma unroll
        for (int v = 0; v < 16; v++) {
            int i = tid + 256 * v;
            int k1 = i >> 5, c1 = (i & 31) * 2;
            *(uint32_t*)(smc + O_W1 + k1 * 144 + c1 * 2) = gw1[i];
            int k2 = i >> 6, c2i = (i & 63) * 2;
            *(uint32_t*)(smc + O_W2 + k2 * 272 + c2i * 2) = gw2[i];
        }
    }

    // ---- per-thread X-loader mapping ----
    const int xr = 0;  // unused placeholder
    (void)xr;

    // preload tile 0 into smem (f32 -> bf16)
    {
        const float4* gX = (const float4*)(X + (size_t)base * TLEN);
        #pragma unroll
        for (int v = 0; v < 8; v++) {
            int idx = tid + 256 * v;
            int r = idx >> 5, c = (idx & 31) * 4;
            float4 x = gX[idx];
            __nv_bfloat162* p = (__nv_bfloat162*)(smc + O_X + r * 272 + c * 2);
            p[0] = __floats2bfloat162_rn(x.x, x.y);
            p[1] = __floats2bfloat162_rn(x.z, x.w);
        }
    }
    __syncthreads();

    const int g = lane >> 2, t = lane & 3;
    const int mt = warp & 3;          // m-tile (16 rows)
    const int nh = warp >> 2;         // n-half
    const int r0 = mt * 16;
    const int am = ((lane >> 3) & 1) * 8 + (lane & 7);
    const int ak = ((lane >> 4) & 1) * 8;
    const int bk = am;
    const int bn = ak;
    const int cb1 = nh * 32;
    const int cb2 = nh * 64;

    // running column maxima across all tiles of this block
    float cm[16];
    #pragma unroll
    for (int j = 0; j < 16; j++) cm[j] = NEGF;

    #pragma unroll 1
    for (int tt = 0; tt < NTILE; tt++) {
        const int row0 = base + tt * 64;

        // prefetch next tile's X into registers (hidden behind this tile's work)
        float4 px[8];
        if (tt < NTILE - 1) {
            const float4* gX = (const float4*)(X + (size_t)(row0 + 64) * TLEN);
            #pragma unroll
            for (int v = 0; v < 8; v++) px[v] = gX[tid + 256 * v];
        }
        // mask for this tile's two rows (L2-resident, issued early)
        const int maskL = __ldg(Mk + row0 + r0 + g);
        const int maskH = __ldg(Mk + row0 + r0 + g + 8);

        // ============ GEMM1: H1[64x64] = X @ W1 ============
        {
            float c1[4][4];
            #pragma unroll
            for (int j = 0; j < 4; j++)
                #pragma unroll
                for (int q = 0; q < 4; q++) c1[j][q] = 0.f;

            uint32_t aB = sb + O_X  + (r0 + am) * 272 + ak * 2;
            uint32_t bB = sb + O_W1 + bk * 144 + (cb1 + bn) * 2;
            #pragma unroll
            for (int ks = 0; ks < 8; ks++) {
                uint32_t a[4], b[8];
                ldmA(a, aB + ks * 32);
                ldmBT(b,     bB + ks * (16 * 144));
                ldmBT(b + 4, bB + ks * (16 * 144) + 32);
                mma16816(c1[0], a, b);
                mma16816(c1[1], a, b + 2);
                mma16816(c1[2], a, b + 4);
                mma16816(c1[3], a, b + 6);
            }
            #pragma unroll
            for (int j = 0; j < 4; j++) {
                int c = cb1 + j * 8 + 2 * t;
                float bb0 = fB1[c], bb1 = fB1[c + 1];
                __nv_bfloat162 lo = __floats2bfloat162_rn(c1[j][0] + bb0, c1[j][1] + bb1);
                __nv_bfloat162 hi = __floats2bfloat162_rn(c1[j][2] + bb0, c1[j][3] + bb1);
                *(__nv_bfloat162*)(smc + O_H1 + (r0 + g) * 144 + c * 2)     = lo;
                *(__nv_bfloat162*)(smc + O_H1 + (r0 + g + 8) * 144 + c * 2) = hi;
            }
        }
        __syncthreads();   // H1 ready; X buffer free after this point

        // ============ GEMM2: H2[64x128] = H1 @ W2 ============
        float c2[8][4];
        #pragma unroll
        for (int j = 0; j < 8; j++)
            #pragma unroll
            for (int q = 0; q < 4; q++) c2[j][q] = 0.f;
        {
            uint32_t aB = sb + O_H1 + (r0 + am) * 144 + ak * 2;
            uint32_t bB = sb + O_W2 + bk * 272 + (cb2 + bn) * 2;
            #pragma unroll
            for (int ks = 0; ks < 4; ks++) {
                uint32_t a[4];
                ldmA(a, aB + ks * 32);
                #pragma unroll
                for (int jj = 0; jj < 4; jj++) {
                    uint32_t b[4];
                    ldmBT(b, bB + ks * (16 * 272) + jj * 32);
                    mma16816(c2[2 * jj],     a, b);
                    mma16816(c2[2 * jj + 1], a, b + 2);
                }
            }
        }

        // ---- +b2, LN partial sums ----
        {
            float sl = 0.f, ql = 0.f, sh = 0.f, qh = 0.f;
            #pragma unroll
            for (int j = 0; j < 8; j++) {
                int c = cb2 + j * 8 + 2 * t;
                float bb0 = fB2[c], bb1 = fB2[c + 1];
                c2[j][0] += bb0; c2[j][1] += bb1;
                c2[j][2] += bb0; c2[j][3] += bb1;
                sl += c2[j][0] + c2[j][1];
                ql += c2[j][0] * c2[j][0] + c2[j][1] * c2[j][1];
                sh += c2[j][2] + c2[j][3];
                qh += c2[j][2] * c2[j][2] + c2[j][3] * c2[j][3];
            }
            #pragma unroll
            for (int s = 1; s <= 2; s <<= 1) {
                sl += __shfl_xor_sync(0xffffffffu, sl, s);
                ql += __shfl_xor_sync(0xffffffffu, ql, s);
                sh += __shfl_xor_sync(0xffffffffu, sh, s);
                qh += __shfl_xor_sync(0xffffffffu, qh, s);
            }
            if (t == 0) {
                fRS[(r0 + g) * 2 + nh] = sl;     fRQ[(r0 + g) * 2 + nh] = ql;
                fRS[(r0 + g + 8) * 2 + nh] = sh; fRQ[(r0 + g + 8) * 2 + nh] = qh;
            }
        }
        __syncthreads();

        if (tid < 64) {
            float S = fRS[tid * 2] + fRS[tid * 2 + 1];
            float Q = fRQ[tid * 2] + fRQ[tid * 2 + 1];
            float mu  = S * 0.0078125f;
            float var = Q * 0.0078125f - mu * mu;
            fMu[tid]  = mu;
            fRsd[tid] = rsqrtf(var + 1e-3f);
        }
        __syncthreads();

        // ---- normalize + relu + mask + store; pool max kept in registers ----
        {
            const float muL = fMu[r0 + g],     rsL = fRsd[r0 + g];
            const float muH = fMu[r0 + g + 8], rsH = fRsd[r0 + g + 8];
            const bool  mkL = (maskL != 0);
            const bool  mkH = (maskH != 0);
            float* oL = out + (size_t)(row0 + r0 + g) * 256;
            float* oH = out + (size_t)(row0 + r0 + g + 8) * 256;

            #pragma unroll
            for (int j = 0; j < 8; j++) {
                int c = cb2 + j * 8 + 2 * t;
                float ga0 = fG[c], ga1 = fG[c + 1];
                float be0 = fBt[c], be1 = fBt[c + 1];

                float vL0 = fmaxf((c2[j][0] - muL) * rsL * ga0 + be0, 0.f);
                float vL1 = fmaxf((c2[j][1] - muL) * rsL * ga1 + be1, 0.f);
                float vH0 = fmaxf((c2[j][2] - muH) * rsH * ga0 + be0, 0.f);
                float vH1 = fmaxf((c2[j][3] - muH) * rsH * ga1 + be1, 0.f);
                vL0 = mkL ? vL0 : NEGF;  vL1 = mkL ? vL1 : NEGF;
                vH0 = mkH ? vH0 : NEGF;  vH1 = mkH ? vH1 : NEGF;

                *(float2*)(oL + c) = make_float2(vL0, vL1);
                *(float2*)(oH + c) = make_float2(vH0, vH1);

                cm[2 * j]     = fmaxf(cm[2 * j],     fmaxf(vL0, vH0));
                cm[2 * j + 1] = fmaxf(cm[2 * j + 1], fmaxf(vL1, vH1));
            }
        }

        // store prefetched X tile (f32 regs -> bf16 smem) for next iteration
        if (tt < NTILE - 1) {
            #pragma unroll
            for (int v = 0; v < 8; v++) {
                int idx = tid + 256 * v;
                int r = idx >> 5, c = (idx & 31) * 4;
                __nv_bfloat162* p = (__nv_bfloat162*)(smc + O_X + r * 272 + c * 2);
                p[0] = __floats2bfloat162_rn(px[v].x, px[v].y);
                p[1] = __floats2bfloat162_rn(px[v].z, px[v].w);
            }
        }
        __syncthreads();
    }

    // ---- once-per-block pool reduction: shuffle over g, then smem atomics ----
    #pragma unroll
    for (int j = 0; j < 16; j++) {
        float v = cm[j];
        #pragma unroll
        for (int s = 4; s <= 16; s <<= 1)
            v = fmaxf(v, __shfl_xor_sync(0xffffffffu, v, s));
        cm[j] = v;
    }
    if (g == 0) {
        #pragma unroll
        for (int j = 0; j < 8; j++) {
            int c = cb2 + j * 8 + 2 * t;
            atomicMax(&iPool[c],     __float_as_int(cm[2 * j]));
            atomicMax(&iPool[c + 1], __float_as_int(cm[2 * j + 1]));
        }
    }
    __syncthreads();

    if (tid < 128)
        atomicMax(&g_pool[bidx * 128 + tid], iPool[tid]);
}

// second half of output: broadcast per-batch pooled max
__global__ void bcast_kernel(float* __restrict__ out) {
    int i   = blockIdx.x * blockDim.x + threadIdx.x;  // over B*N*32 float4s
    int d4  = (i & 31) << 2;
    int row = i >> 5;
    int bb  = row >> 11;
    int4 p = *(const int4*)(g_pool + bb * 128 + d4);
    float4 v = make_float4(__int_as_float(p.x), __int_as_float(p.y),
                           __int_as_float(p.z), __int_as_float(p.w));
    *(float4*)(out + (size_t)row * 256 + 128 + d4) = v;
}

extern "C" void kernel_launch(void* const* d_in, const int* in_sizes, int n_in,
                              void* d_out, int out_size) {
    const float* X  = (const float*)d_in[0];
    const int*   Mk = (const int*)  d_in[1];
    const float* W1 = (const float*)d_in[2];
    const float* b1 = (const float*)d_in[3];
    const float* W2 = (const float*)d_in[4];
    const float* b2 = (const float*)d_in[5];
    const float* g  = (const float*)d_in[6];
    const float* bt = (const float*)d_in[7];
    float* out = (float*)d_out;

    cudaFuncSetAttribute(fused_mlp_kernel,
                         cudaFuncAttributeMaxDynamicSharedMemorySize, SMEM_BYTES);

    prep_kernel<<<(TB * TLEN + 255) / 256, 256>>>(W1, W2);
    fused_mlp_kernel<<<(TB * TN) / ROWS_PB, 256, SMEM_BYTES>>>(
        X, Mk, b1, b2, g, bt, out);
    bcast_kernel<<<(TB * TN * 32) / 256, 256>>>(out);
}